// round 17
// baseline (speedup 1.0000x reference)
#include <cuda_runtime.h>
#include <cuda_bf16.h>
#include <cstdint>

// Involution: B=4, C=256, G=16, K=7, S=1, P=3, H=W=56
#define HW 3136
#define XCH 634    // xt per-channel stride (floats)
#define KSTR 228   // kern row stride (floats)

// h^T[b][px][64o] bf16 hi/lo, rows of 128B stored PRE-SWIZZLED (SW128)
__device__ uint4 g_ht_hi[4 * HW * 8];    // 4*HW rows * 128B
__device__ uint4 g_ht_lo[4 * HW * 8];
// span_w image: bf16 hi/lo, SW128 pre-swizzled rows of 128B (built by reduce_mma)
__device__ uint4 g_sw_img_hi[8192];      // [16 g][64 row][64 c] = 128KB
__device__ uint4 g_sw_img_lo[8192];

// ---- f32x2 helpers ----
union F2 { float2 f; unsigned long long u; };
union F4 { float4 f; unsigned long long u[2]; };
__device__ __forceinline__ unsigned long long pk2f(float lo, float hi) {
    unsigned long long d;
    asm("mov.b64 %0, {%1, %2};" : "=l"(d) : "f"(lo), "f"(hi));
    return d;
}
__device__ __forceinline__ unsigned long long ffma2(
    unsigned long long a, unsigned long long b, unsigned long long c) {
    unsigned long long d;
    asm("fma.rn.f32x2 %0, %1, %2, %3;" : "=l"(d) : "l"(a), "l"(b), "l"(c));
    return d;
}

// ---- mma / ldmatrix / cp.async helpers ----
__device__ __forceinline__ uint32_t smem_u32(const void* p) {
    uint32_t a;
    asm("{ .reg .u64 t; cvta.to.shared.u64 t, %1; cvt.u32.u64 %0, t; }" : "=r"(a) : "l"(p));
    return a;
}
#define SWZ(o) ((o) ^ (((o) >> 3) & 0x70))
__device__ __forceinline__ void ldsm4(uint32_t* r, uint32_t addr) {
    asm volatile("ldmatrix.sync.aligned.m8n8.x4.shared.b16 {%0,%1,%2,%3}, [%4];"
        : "=r"(r[0]), "=r"(r[1]), "=r"(r[2]), "=r"(r[3]) : "r"(addr));
}
__device__ __forceinline__ void ldsm4t(uint32_t* r, uint32_t addr) {
    asm volatile("ldmatrix.sync.aligned.m8n8.x4.trans.shared.b16 {%0,%1,%2,%3}, [%4];"
        : "=r"(r[0]), "=r"(r[1]), "=r"(r[2]), "=r"(r[3]) : "r"(addr));
}
__device__ __forceinline__ void mma_bf16(float* c, const uint32_t* a, const uint32_t* b) {
    asm volatile("mma.sync.aligned.m16n8k16.row.col.f32.bf16.bf16.f32 "
        "{%0,%1,%2,%3}, {%4,%5,%6,%7}, {%8,%9}, {%0,%1,%2,%3};"
        : "+f"(c[0]), "+f"(c[1]), "+f"(c[2]), "+f"(c[3])
        : "r"(a[0]), "r"(a[1]), "r"(a[2]), "r"(a[3]), "r"(b[0]), "r"(b[1]));
}
__device__ __forceinline__ void cp_async4(uint32_t dst, const void* src, bool pred) {
    int sz = pred ? 4 : 0;
    asm volatile("cp.async.ca.shared.global [%0], [%1], 4, %2;"
                 :: "r"(dst), "l"(src), "r"(sz) : "memory");
}

__device__ __forceinline__ void split_bf16x4(const float4& v, uint2& H, uint2& L) {
    __nv_bfloat162 h0 = __floats2bfloat162_rn(v.x, v.y);
    __nv_bfloat162 h1 = __floats2bfloat162_rn(v.z, v.w);
    __nv_bfloat162 l0 = __floats2bfloat162_rn(v.x - __bfloat162float(h0.x),
                                              v.y - __bfloat162float(h0.y));
    __nv_bfloat162 l1 = __floats2bfloat162_rn(v.z - __bfloat162float(h1.x),
                                              v.w - __bfloat162float(h1.y));
    union { __nv_bfloat162 b2[2]; uint2 u; } t;
    t.b2[0] = h0; t.b2[1] = h1; H = t.u;
    t.b2[0] = l0; t.b2[1] = l1; L = t.u;
}

// ---------------------------------------------------------------------------
// Kernel 1 (HMMA): h^T[b][px][o] = rw @ x, grid (28,4), 256 thr.
// B (x) hi/lo fragments fetched with ONE merged ldmatrix.x4.trans.
// ---------------------------------------------------------------------------
#define R_RWHI 0
#define R_RWLO 32768
#define R_XBHI 65536               // 256 rows x 240B = 61440
#define R_XBLO 126976
#define R_T    65536               // overlay: 112*68*4 = 30464
#define R_RB   188416              // 64 floats
#define R_TOTAL 188672

__global__ __launch_bounds__(256) void reduce_mma(
    const float* __restrict__ x,
    const float* __restrict__ rw,
    const float* __restrict__ sw,
    const float* __restrict__ rb)
{
    const int b  = blockIdx.y;
    const int n0 = blockIdx.x * 112;
    extern __shared__ char smem[];
    const int tid = threadIdx.x;
    const uint32_t sbase = smem_u32(smem);
    float* rbs = (float*)(smem + R_RB);

    // rw -> smem bf16 hi/lo, SW128 swizzled (inline conversion, coalesced)
    #pragma unroll
    for (int i = 0; i < 16; i++) {
        int e4 = tid + i * 256;
        int o = e4 >> 6;
        int c = (e4 & 63) * 4;
        int chunk = c >> 6, cl = c & 63;
        float4 v = *(const float4*)&rw[e4 * 4];
        uint2 H, L;
        split_bf16x4(v, H, L);
        int byte = chunk * 8192 + o * 128 + ((cl * 2) ^ ((o & 7) << 4));
        *(uint2*)(smem + R_RWHI + byte) = H;
        *(uint2*)(smem + R_RWLO + byte) = L;
    }
    if (tid < 64) rbs[tid] = rb[tid];

    // build span_w global image for inv
    {
        const int gtid = (blockIdx.y * 28 + blockIdx.x) * 256 + tid;
        #pragma unroll
        for (int e = gtid; e < 65536; e += 28672) {
            int g = e >> 12, rem = e & 4095;
            int r = rem >> 6, c = rem & 63;
            float v = (r < 49) ? sw[g * 3136 + r * 64 + c] : 0.f;
            __nv_bfloat16 h = __float2bfloat16(v);
            __nv_bfloat16 l = __float2bfloat16(v - __bfloat162float(h));
            int byte = g * 8192 + r * 128 + ((c * 2) ^ ((r & 7) << 4));
            *(__nv_bfloat16*)((char*)g_sw_img_hi + byte) = h;
            *(__nv_bfloat16*)((char*)g_sw_img_lo + byte) = l;
        }
    }

    // stage x -> bf16 hi/lo [c][px] rows of 240B
    for (int e4 = tid; e4 < 7168; e4 += 256) {
        int c = e4 / 28, p4 = (e4 - c * 28) * 4;
        float4 v = *(const float4*)&x[(size_t)(b * 256 + c) * HW + n0 + p4];
        uint2 H, L;
        split_bf16x4(v, H, L);
        *(uint2*)(smem + R_XBHI + c * 240 + p4 * 2) = H;
        *(uint2*)(smem + R_XBLO + c * 240 + p4 * 2) = L;
    }
    __syncthreads();

    // GEMM: 8 warps = 4 mt x 2 nh; acc[7 n-tiles][4]
    const int wrp = tid >> 5, lane = tid & 31;
    const int mt = wrp >> 1, nh = wrp & 1;
    float acc[7][4];
    #pragma unroll
    for (int j = 0; j < 7; j++)
        #pragma unroll
        for (int q = 0; q < 4; q++) acc[j][q] = 0.f;

    const uint32_t a_off = (uint32_t)((mt * 16 + (lane & 15)) * 128 + ((lane & 16) ? 16 : 0));
    // merged B x4.trans: lanes 0-15 -> XBHI rows, lanes 16-31 -> XBLO rows
    const uint32_t xb_base = (lane < 16) ? (uint32_t)R_XBHI : (uint32_t)R_XBLO;
    const uint32_t xb_lane = (uint32_t)((lane & 15) * 240);

    #pragma unroll 1
    for (int kt = 0; kt < 16; kt++) {
        const int q = kt >> 2, ktl = kt & 3;
        uint32_t ahi[4], alo[4];
        ldsm4(ahi, sbase + R_RWHI + q * 8192 + SWZ(a_off + ktl * 32));
        ldsm4(alo, sbase + R_RWLO + q * 8192 + SWZ(a_off + ktl * 32));
        const uint32_t brow = xb_base + (uint32_t)(kt * 16 * 240) + xb_lane;
        #pragma unroll
        for (int j = 0; j < 7; j++) {
            const uint32_t pxo = (uint32_t)(((nh * 7 + j) * 8) * 2);
            uint32_t bf[4];                 // {bh0, bh1, bl0, bl1}
            ldsm4t(bf, sbase + brow + pxo);
            mma_bf16(acc[j], ahi, bf);      // hi*hi
            mma_bf16(acc[j], ahi, bf + 2);  // hi*lo
            mma_bf16(acc[j], alo, bf);      // lo*hi
        }
    }
    __syncthreads();

    // transpose through T[112px][68]
    {
        float* T = (float*)(smem + R_T);
        const int gq = lane >> 2, tig = lane & 3;
        const int o = mt * 16 + gq;
        #pragma unroll
        for (int j = 0; j < 7; j++) {
            const int px0 = (nh * 7 + j) * 8 + 2 * tig;
            T[px0 * 68 + o]           = acc[j][0];
            T[(px0 + 1) * 68 + o]     = acc[j][1];
            T[px0 * 68 + o + 8]       = acc[j][2];
            T[(px0 + 1) * 68 + o + 8] = acc[j][3];
        }
    }
    __syncthreads();

    // final: +bias, bf16 hi/lo, pre-swizzled STG
    {
        const float* T = (const float*)(smem + R_T);
        for (int e2 = tid; e2 < 1792; e2 += 256) {
            int px = e2 >> 4, o4 = (e2 & 15) * 4;
            float4 v = *(const float4*)&T[px * 68 + o4];
            v.x += rbs[o4]; v.y += rbs[o4 + 1]; v.z += rbs[o4 + 2]; v.w += rbs[o4 + 3];
            uint2 H, L;
            split_bf16x4(v, H, L);
            size_t rowb = (size_t)(b * HW + n0 + px) * 128;
            int swo = (o4 * 2) ^ (((n0 + px) & 7) << 4);
            *(uint2*)((char*)g_ht_hi + rowb + swo) = H;
            *(uint2*)((char*)g_ht_lo + rowb + swo) = L;
        }
    }
}

// ---------------------------------------------------------------------------
// Kernel 2: HMMA span GEMM + fp32 apply.
// Warp remap 2mt x 4ng (B redundancy 4x -> 2x); hi/lo B in one ldmatrix.x4.
// ---------------------------------------------------------------------------
#define SM_WS_HI 0
#define SM_WS_LO 8192
#define SM_H_HI  16384
#define SM_H_LO  45056
#define SM_KERN  16384
#define SM_XT    73728
#define SM_SB    114304
#define SM_TOTAL 114560

__global__ __launch_bounds__(256, 2) void inv_kernel(
    const float* __restrict__ x,
    const float* __restrict__ sw,
    const float* __restrict__ sb,
    float* __restrict__ out)
{
    const int r0 = blockIdx.x * 4;
    const int g  = blockIdx.y;
    const int b  = blockIdx.z;

    extern __shared__ char smem[];
    const int tid = threadIdx.x;
    const uint32_t sbase = smem_u32(smem);
    const int wrp = tid >> 5, lane = tid & 31;

    float* kernsm = (float*)(smem + SM_KERN);
    float* xt     = (float*)(smem + SM_XT);
    float* sbias  = (float*)(smem + SM_SB);

    // ---- issue xt halo cp.asyncs FIRST (consumed only in phase 2) ----
    {
        const float* xg = &x[(size_t)(b * 256 + g * 16) * HW];
        #pragma unroll 1
        for (int it = 0; it < 20; it++) {
            int job = it * 8 + wrp;            // (ch, halo-row), 0..159
            int ch = job / 10, rr = job - ch * 10;
            int gr = r0 + rr - 3;
            bool rok = (gr >= 0) && (gr < 56);
            const float* xrow = xg + (size_t)ch * HW + (rok ? gr * 56 : 0);
            uint32_t drow = sbase + SM_XT + 4 * (ch * XCH + rr * 62);
            int c0 = lane, c1 = lane + 32;
            int g0 = c0 - 3, g1 = c1 - 3;
            bool ok0 = rok && (g0 >= 0) && (g0 < 56);
            bool ok1 = rok && (g1 < 56);
            cp_async4(drow + 4 * c0, xrow + (ok0 ? g0 : 0), ok0);
            if (c1 < 62)
                cp_async4(drow + 4 * c1, xrow + (ok1 ? g1 : 0), ok1);
        }
        asm volatile("cp.async.commit_group;" ::: "memory");
    }

    // ---- ws image copy (pre-swizzled) ----
    {
        uint4* sh = (uint4*)(smem + SM_WS_HI);
        uint4* sl = (uint4*)(smem + SM_WS_LO);
        const uint4* gh = g_sw_img_hi + g * 512;
        const uint4* gl = g_sw_img_lo + g * 512;
        #pragma unroll
        for (int i = 0; i < 2; i++) {
            int e = tid + i * 256;
            sh[e] = gh[e];
            sl[e] = gl[e];
        }
    }
    if (tid < 49) sbias[tid] = sb[g * 49 + tid];

    // ---- h tile copy (pre-swizzled rows) ----
    {
        const uint4* bh = g_ht_hi + (size_t)(b * HW + r0 * 56) * 8;
        const uint4* bl = g_ht_lo + (size_t)(b * HW + r0 * 56) * 8;
        uint4* sh = (uint4*)(smem + SM_H_HI);
        uint4* sl = (uint4*)(smem + SM_H_LO);
        #pragma unroll
        for (int i = 0; i < 7; i++) {
            int e = tid + i * 256;
            sh[e] = bh[e];
            sl[e] = bl[e];
        }
    }
    __syncthreads();   // ws + h visible (xt still in flight)

    // ---- Phase 1: HMMA GEMM kern[64][224], warps = 2mt x 4ng ----
    const int mth = wrp >> 2;          // 0..1 : m-tiles {2*mth, 2*mth+1}
    const int ng  = wrp & 3;           // 0..3 : n-tiles ng*7 .. ng*7+6

    float acc[2][7][4];
    #pragma unroll
    for (int m = 0; m < 2; m++)
        #pragma unroll
        for (int j = 0; j < 7; j++)
            #pragma unroll
            for (int q = 0; q < 4; q++) acc[m][j][q] = 0.f;

    uint32_t a_off[2];
    #pragma unroll
    for (int m = 0; m < 2; m++)
        a_off[m] = (uint32_t)(((2 * mth + m) * 16 + (lane & 15)) * 128 + ((lane & 16) ? 16 : 0));
    // merged B x4: lanes 0-15 -> H_HI, lanes 16-31 -> H_LO
    const uint32_t hb_base = (lane < 16) ? (uint32_t)SM_H_HI : (uint32_t)SM_H_LO;
    const uint32_t hb_lane = (uint32_t)((lane & 7) * 128 + ((lane & 8) ? 16 : 0));

    #pragma unroll
    for (int kt = 0; kt < 4; kt++) {
        uint32_t ahi[2][4], alo[2][4];
        #pragma unroll
        for (int m = 0; m < 2; m++) {
            ldsm4(ahi[m], sbase + SM_WS_HI + SWZ(a_off[m] + kt * 32));
            ldsm4(alo[m], sbase + SM_WS_LO + SWZ(a_off[m] + kt * 32));
        }
        #pragma unroll
        for (int j = 0; j < 7; j++) {
            uint32_t boff = SWZ(hb_lane + (uint32_t)((ng * 7 + j) * 1024) + kt * 32);
            uint32_t bf[4];                 // {bh0, bh1, bl0, bl1}
            ldsm4(bf, sbase + hb_base + boff);
            #pragma unroll
            for (int m = 0; m < 2; m++) {
                mma_bf16(acc[m][j], ahi[m], bf);
                mma_bf16(acc[m][j], ahi[m], bf + 2);
                mma_bf16(acc[m][j], alo[m], bf);
            }
        }
    }
    __syncthreads();   // all h reads done before kern overlay writes

    // ---- epilogue: fragments + bias -> kern smem ----
    {
        const int gq = lane >> 2, tig = lane & 3;
        #pragma unroll
        for (int m = 0; m < 2; m++) {
            const int kk0 = (2 * mth + m) * 16 + gq;
            const int kk1 = kk0 + 8;
            const float b0 = (kk0 < 49) ? sbias[kk0] : 0.f;
            const float b1 = (kk1 < 49) ? sbias[kk1] : 0.f;
            #pragma unroll
            for (int j = 0; j < 7; j++) {
                const int px = (ng * 7 + j) * 8 + 2 * tig;
                if (kk0 < 49) {
                    float2 v = {acc[m][j][0] + b0, acc[m][j][1] + b0};
                    *(float2*)&kernsm[kk0 * KSTR + px] = v;
                }
                if (kk1 < 49) {
                    float2 v = {acc[m][j][2] + b1, acc[m][j][3] + b1};
                    *(float2*)&kernsm[kk1 * KSTR + px] = v;
                }
            }
        }
    }
    asm volatile("cp.async.wait_group 0;" ::: "memory");   // xt landed
    __syncthreads();

    // ---- Phase 2: apply. thread = 4 px x 4 interleaved channels ----
    if (tid < 224) {
        const int pd  = tid >> 2;
        const int cq  = tid & 3;
        const int lr  = pd / 14;
        const int pc4 = pd - lr * 14;
        const int pix0 = 4 * pd;
        const int col0 = 4 * pc4;
        const int row  = r0 + lr;

        unsigned long long acc2[4][2];
        #pragma unroll
        for (int i = 0; i < 4; i++)
            #pragma unroll
            for (int j = 0; j < 2; j++) acc2[i][j] = 0ull;

        #pragma unroll 1
        for (int kh = 0; kh < 7; kh++) {
            unsigned long long kc2[7][2];
            #pragma unroll
            for (int kw = 0; kw < 7; kw++) {
                F4 t;
                t.f = *(const float4*)&kernsm[(kh * 7 + kw) * KSTR + pix0];
                kc2[kw][0] = t.u[0];
                kc2[kw][1] = t.u[1];
            }

            #pragma unroll
            for (int i = 0; i < 4; i++) {
                const int ch = cq + 4 * i;
                const float* xr = &xt[ch * XCH + (lr + kh) * 62 + col0];
                F2 P[5];
                #pragma unroll
                for (int s = 0; s < 5; s++) P[s].f = *(const float2*)&xr[2 * s];
                unsigned long long M[4];
                #pragma unroll
                for (int s = 0; s < 4; s++) M[s] = pk2f(P[s].f.y, P[s + 1].f.x);

                acc2[i][0] = ffma2(kc2[0][0], P[0].u, acc2[i][0]);
                acc2[i][0] = ffma2(kc2[1][0], M[0],   acc2[i][0]);
                acc2[i][0] = ffma2(kc2[2][0], P[1].u, acc2[i][0]);
                acc2[i][0] = ffma2(kc2[3][0], M[1],   acc2[i][0]);
                acc2[i][0] = ffma2(kc2[4][0], P[2].u, acc2[i][0]);
                acc2[i][0] = ffma2(kc2[5][0], M[2],   acc2[i][0]);
                acc2[i][0] = ffma2(kc2[6][0], P[3].u, acc2[i][0]);

                acc2[i][1] = ffma2(kc2[0][1], P[1].u, acc2[i][1]);
                acc2[i][1] = ffma2(kc2[1][1], M[1],   acc2[i][1]);
                acc2[i][1] = ffma2(kc2[2][1], P[2].u, acc2[i][1]);
                acc2[i][1] = ffma2(kc2[3][1], M[2],   acc2[i][1]);
                acc2[i][1] = ffma2(kc2[4][1], P[3].u, acc2[i][1]);
                acc2[i][1] = ffma2(kc2[5][1], M[3],   acc2[i][1]);
                acc2[i][1] = ffma2(kc2[6][1], P[4].u, acc2[i][1]);
            }
        }

        #pragma unroll
        for (int i = 0; i < 4; i++) {
            const int ch = cq + 4 * i;
            #pragma unroll
            for (int j = 0; j < 2; j++) {
                F2 r; r.u = acc2[i][j];
                *(float2*)&out[(size_t)(b * 256 + g * 16 + ch) * HW + row * 56 + col0 + 2 * j] = r.f;
            }
        }
    }
}

extern "C" void kernel_launch(void* const* d_in, const int* in_sizes, int n_in,
                              void* d_out, int out_size)
{
    const float* x  = (const float*)d_in[0];
    const float* rw = (const float*)d_in[1];
    const float* rb = (const float*)d_in[2];
    const float* sw = (const float*)d_in[3];
    const float* sb = (const float*)d_in[4];
    float* out = (float*)d_out;

    cudaFuncSetAttribute(reduce_mma, cudaFuncAttributeMaxDynamicSharedMemorySize, R_TOTAL);
    cudaFuncSetAttribute(inv_kernel, cudaFuncAttributeMaxDynamicSharedMemorySize, SM_TOTAL);

    reduce_mma<<<dim3(28, 4), 256, R_TOTAL>>>(x, rw, sw, rb);
    inv_kernel<<<dim3(14, 16, 4), 256, SM_TOTAL>>>(x, sw, sb, out);
}